// round 8
// baseline (speedup 1.0000x reference)
#include <cuda_runtime.h>
#include <cstdint>

#define B_SZ    2
#define S_LEN   2048
#define D_MODEL 1024
#define NHEADS  16
#define DK      64
#define M_ROWS  (B_SZ * S_LEN)     // 4096
#define QKV_N   (3 * D_MODEL)      // 3072

// Scratch (alloc-free: __device__ globals)
__device__ float g_qkv[(size_t)M_ROWS * QKV_N];     // rounded qkv (token-major)
__device__ float g_ctx[(size_t)M_ROWS * D_MODEL];   // rounded ctx
__device__ float g_xr [(size_t)M_ROWS * D_MODEL];   // rounded x
__device__ float g_wqt[(size_t)QKV_N * D_MODEL];    // rounded W_qkv^T [N][K]
__device__ float g_wot[(size_t)D_MODEL * D_MODEL];  // rounded W_o^T  [N][K]
__device__ float g_vt [(size_t)B_SZ * NHEADS * DK * S_LEN]; // V^T per (b,h): [dk][seq]

// ---------------------------------------------------------------------------
// helpers
// ---------------------------------------------------------------------------
__device__ __forceinline__ float f2tf_f(float f) {
    unsigned u;
    asm("cvt.rna.tf32.f32 %0, %1;" : "=r"(u) : "f"(f));
    return __uint_as_float(u);
}
__device__ __forceinline__ unsigned f2tf(float f) {
    unsigned u;
    asm("cvt.rna.tf32.f32 %0, %1;" : "=r"(u) : "f"(f));
    return u;
}
__device__ __forceinline__ uint32_t smem_u32(const void* p) {
    uint32_t a;
    asm("{ .reg .u64 t; cvta.to.shared.u64 t, %1; cvt.u32.u64 %0, t; }"
        : "=r"(a) : "l"(p));
    return a;
}

#define CP_ASYNC16(dst, src) \
    asm volatile("cp.async.cg.shared.global [%0], [%1], 16;" :: "r"(dst), "l"(src))
#define CP_COMMIT() asm volatile("cp.async.commit_group;" ::: "memory")
#define CP_WAIT1()  asm volatile("cp.async.wait_group 1;" ::: "memory")

#define LDSM_X4(r0, r1, r2, r3, addr) \
    asm volatile("ldmatrix.sync.aligned.m8n8.x4.shared.b16 {%0,%1,%2,%3}, [%4];" \
                 : "=r"(r0), "=r"(r1), "=r"(r2), "=r"(r3) : "r"(addr))

__device__ __forceinline__ void mma_tf32(float* c, const unsigned* a,
                                         unsigned b0, unsigned b1) {
    asm volatile(
        "mma.sync.aligned.m16n8k8.row.col.f32.tf32.tf32.f32 "
        "{%0,%1,%2,%3}, {%4,%5,%6,%7}, {%8,%9}, {%0,%1,%2,%3};\n"
        : "+f"(c[0]), "+f"(c[1]), "+f"(c[2]), "+f"(c[3])
        : "r"(a[0]), "r"(a[1]), "r"(a[2]), "r"(a[3]), "r"(b0), "r"(b1));
}

// ---------------------------------------------------------------------------
// prep kernels
// ---------------------------------------------------------------------------
__global__ void __launch_bounds__(256)
k_round4(const float* __restrict__ in, float* __restrict__ out, int n4)
{
    int i = blockIdx.x * 256 + threadIdx.x;
    if (i < n4) {
        float4 v = ((const float4*)in)[i];
        v.x = f2tf_f(v.x); v.y = f2tf_f(v.y);
        v.z = f2tf_f(v.z); v.w = f2tf_f(v.w);
        ((float4*)out)[i] = v;
    }
}

// round + transpose: in [R][C] -> out [C][R]
__global__ void __launch_bounds__(256)
k_trT(const float* __restrict__ in, float* __restrict__ out, int R, int C)
{
    __shared__ float tile[32][33];
    const int tx = threadIdx.x, ty = threadIdx.y;
    const int c0 = blockIdx.x * 32, r0 = blockIdx.y * 32;
    #pragma unroll
    for (int i = 0; i < 32; i += 8)
        tile[ty + i][tx] = f2tf_f(in[(size_t)(r0 + ty + i) * C + c0 + tx]);
    __syncthreads();
    #pragma unroll
    for (int i = 0; i < 32; i += 8)
        out[(size_t)(c0 + ty + i) * R + r0 + tx] = tile[tx][ty + i];
}

// V transpose: g_qkv V-slices (token-major) -> g_vt [(bh*64+d)][token]
__global__ void __launch_bounds__(256)
k_vtrans()
{
    __shared__ float tile[32][33];
    const int tx = threadIdx.x, ty = threadIdx.y;
    const int t0 = blockIdx.x * 32;          // token tile
    const int d0 = blockIdx.y * 32;          // d tile (0 or 32)
    const int bh = blockIdx.z;               // 0..31
    const int b = bh >> 4, h = bh & 15;
    const float* src = g_qkv + (size_t)b * S_LEN * QKV_N + h * 192 + 128;
    #pragma unroll
    for (int i = 0; i < 32; i += 8)
        tile[ty + i][tx] = src[(size_t)(t0 + ty + i) * QKV_N + d0 + tx];
    __syncthreads();
    float* dst = g_vt + ((size_t)bh * DK + d0) * S_LEN + t0;
    #pragma unroll
    for (int i = 0; i < 32; i += 8)
        dst[(size_t)(ty + i) * S_LEN + tx] = tile[tx][ty + i];
}

// ---------------------------------------------------------------------------
// TF32 GEMM: C[M,N] = A[M,K] @ BT[N,K]^T + bias[N]
// Block 128x128, BK=32, 3-stage cp.async, 256 threads = 8 warps (4M x 2N),
// warp tile 32x64. Both smem tiles k-contiguous (stride 36 words, ==4 mod 32:
// ldmatrix conflict-free). All fragments via ldmatrix.x4.
// ---------------------------------------------------------------------------
#define TS_STR 36
#define STG_W  (128 * TS_STR)            // words per (A or B) per stage: 4608
#define ABUF(s) ((s) * 2 * STG_W)
#define BBUF(s) ((s) * 2 * STG_W + STG_W)
#define GT_SMEM (3 * 2 * STG_W * 4)      // 110592 B

template <bool ROUND>
__global__ void __launch_bounds__(256, 1)
k_gemm(const float* __restrict__ A, const float* __restrict__ BT,
       const float* __restrict__ bias, float* __restrict__ C,
       int N, int K)
{
    extern __shared__ unsigned smw[];
    const uint32_t sb = smem_u32(smw);
    const int tid  = threadIdx.x;
    const int wid  = tid >> 5;
    const int lane = tid & 31;
    const int lr   = lane >> 2;
    const int lc   = lane & 3;
    const int wm   = (wid & 3) * 32;
    const int wn   = (wid >> 2) * 64;
    const int bm   = blockIdx.y * 128;
    const int bn   = blockIdx.x * 128;

    float acc[2][8][4];
    #pragma unroll
    for (int i = 0; i < 2; i++)
        #pragma unroll
        for (int j = 0; j < 8; j++)
            #pragma unroll
            for (int q = 0; q < 4; q++) acc[i][j][q] = 0.f;

    // cp.async indices: 1024 chunks of 16B per operand per stage, 4/thread
    const int ldRow = tid >> 1;            // 0..127
    const int ldCol = (tid & 1) * 16;      // word col 0 or 16

    auto issue = [&](int t) {
        const int s  = t % 3;
        const int k0 = t * 32;
        const float* ap = A  + (size_t)(bm + ldRow) * K + k0 + ldCol;
        const float* bp = BT + (size_t)(bn + ldRow) * K + k0 + ldCol;
        const uint32_t da = sb + (ABUF(s) + ldRow * TS_STR + ldCol) * 4;
        const uint32_t db = sb + (BBUF(s) + ldRow * TS_STR + ldCol) * 4;
        CP_ASYNC16(da,      ap);
        CP_ASYNC16(da + 16, ap + 4);
        CP_ASYNC16(da + 32, ap + 8);
        CP_ASYNC16(da + 48, ap + 12);
        CP_ASYNC16(db,      bp);
        CP_ASYNC16(db + 16, bp + 4);
        CP_ASYNC16(db + 32, bp + 8);
        CP_ASYNC16(db + 48, bp + 12);
    };

    // ldmatrix per-lane base offsets (in words)
    const int aRow = wm + (lane & 15);
    const int aCw  = (lane >> 4) * 4;
    const int aOff0 = aRow * TS_STR + aCw;            // i = 0
    const int aOff1 = (aRow + 16) * TS_STR + aCw;     // i = 1
    const int mi   = lane >> 3;                        // 0..3
    const int bRow = wn + ((mi >> 1) * 8) + (lane & 7);
    const int bCw  = (mi & 1) * 4;

    const int nT = K / 32;
    issue(0); CP_COMMIT();
    issue(1); CP_COMMIT();

    for (int t = 0; t < nT; t++) {
        CP_WAIT1();
        __syncthreads();
        const int s = t % 3;
        const uint32_t aBase = sb + (ABUF(s)) * 4;
        const uint32_t bBase = sb + (BBUF(s)) * 4;

        #pragma unroll
        for (int kk = 0; kk < 4; kk++) {
            unsigned af0[4], af1[4];
            LDSM_X4(af0[0], af0[1], af0[2], af0[3], aBase + (aOff0 + 8 * kk) * 4);
            LDSM_X4(af1[0], af1[1], af1[2], af1[3], aBase + (aOff1 + 8 * kk) * 4);
            #pragma unroll
            for (int p = 0; p < 4; p++) {          // j pairs
                unsigned bf[4];
                LDSM_X4(bf[0], bf[1], bf[2], bf[3],
                        bBase + (bRow * TS_STR + 16 * p * TS_STR + bCw + 8 * kk) * 4);
                mma_tf32(acc[0][2 * p],     af0, bf[0], bf[1]);
                mma_tf32(acc[1][2 * p],     af1, bf[0], bf[1]);
                mma_tf32(acc[0][2 * p + 1], af0, bf[2], bf[3]);
                mma_tf32(acc[1][2 * p + 1], af1, bf[2], bf[3]);
            }
        }
        if (t + 2 < nT) issue(t + 2);
        CP_COMMIT();
    }

    #pragma unroll
    for (int j = 0; j < 8; j++) {
        const int col = bn + wn + 8 * j + 2 * lc;
        const float bs0 = bias[col], bs1 = bias[col + 1];
        #pragma unroll
        for (int i = 0; i < 2; i++) {
            const int row = bm + wm + 16 * i + lr;
            float2 r0, r1;
            if (ROUND) {
                r0 = make_float2(f2tf_f(acc[i][j][0] + bs0), f2tf_f(acc[i][j][1] + bs1));
                r1 = make_float2(f2tf_f(acc[i][j][2] + bs0), f2tf_f(acc[i][j][3] + bs1));
            } else {
                r0 = make_float2(acc[i][j][0] + bs0, acc[i][j][1] + bs1);
                r1 = make_float2(acc[i][j][2] + bs0, acc[i][j][3] + bs1);
            }
            *(float2*)(C + (size_t)row * N + col) = r0;
            *(float2*)(C + (size_t)(row + 8) * N + col) = r1;
        }
    }
}

// ---------------------------------------------------------------------------
// Flash attention: 256 threads (8 warps) = 128 q-rows, 64-key tiles,
// 3-stage cp.async for K (from g_qkv) and V^T (from g_vt).
// All B/A fragments via ldmatrix.x4. P bounced via smem (warp-private rows).
// Strides 68 words (==4 mod 32, ldmatrix conflict-free).
// ---------------------------------------------------------------------------
#define AS2_STR 68
#define KOFF(s) ((s) * 2 * 64 * AS2_STR)
#define VOFF(s) ((s) * 2 * 64 * AS2_STR + 64 * AS2_STR)
#define POFF    (3 * 2 * 64 * AS2_STR)                 // 26112 words
#define AT_SMEM ((POFF + 128 * AS2_STR) * 4)           // 139264 B

__global__ void __launch_bounds__(256, 1)
k_attn()
{
    extern __shared__ unsigned smw[];
    const uint32_t sb = smem_u32(smw);
    const int tid  = threadIdx.x;
    const int wid  = tid >> 5;
    const int lane = tid & 31;
    const int lr   = lane >> 2;
    const int lc   = lane & 3;
    const int bh   = blockIdx.x;
    const int b    = bh >> 4;
    const int h    = bh & 15;
    const int q0   = blockIdx.y * 128;

    const float* base = g_qkv + (size_t)b * S_LEN * QKV_N;
    const float* vtb  = g_vt + (size_t)bh * DK * S_LEN;
    const int ho = h * (3 * DK);

    // Q fragments (g_qkv pre-rounded; x0.125 exact)
    unsigned Qf[8][4];
    {
        const float* qr0 = base + (size_t)(q0 + wid * 16 + lr) * QKV_N + ho;
        const float* qr1 = qr0 + (size_t)8 * QKV_N;
        #pragma unroll
        for (int kk = 0; kk < 8; kk++) {
            Qf[kk][0] = __float_as_uint(0.125f * qr0[8 * kk + lc]);
            Qf[kk][1] = __float_as_uint(0.125f * qr1[8 * kk + lc]);
            Qf[kk][2] = __float_as_uint(0.125f * qr0[8 * kk + lc + 4]);
            Qf[kk][3] = __float_as_uint(0.125f * qr1[8 * kk + lc + 4]);
        }
    }

    // cp.async: K and V^T each 64 rows x 16 chunks (1024); 4 chunks/thread each
    auto issue = [&](int t) {
        const int s  = t % 3;
        const int r  = tid >> 2;            // row 0..63
        const int cb = (tid & 3) * 16;      // word col 0/16/32/48
        {   // K tile: rows = keys, cols = dims (64 words)
            const float* kp = base + (size_t)(t * 64 + r) * QKV_N + ho + DK + cb;
            const uint32_t dk_ = sb + (KOFF(s) + r * AS2_STR + cb) * 4;
            CP_ASYNC16(dk_,      kp);
            CP_ASYNC16(dk_ + 16, kp + 4);
            CP_ASYNC16(dk_ + 32, kp + 8);
            CP_ASYNC16(dk_ + 48, kp + 12);
        }
        {   // V^T tile: rows = dims, cols = keys (64 words)
            const float* vp = vtb + (size_t)r * S_LEN + t * 64 + cb;
            const uint32_t dv = sb + (VOFF(s) + r * AS2_STR + cb) * 4;
            CP_ASYNC16(dv,      vp);
            CP_ASYNC16(dv + 16, vp + 4);
            CP_ASYNC16(dv + 32, vp + 8);
            CP_ASYNC16(dv + 48, vp + 12);
        }
    };

    float oAcc[8][4];
    #pragma unroll
    for (int j = 0; j < 8; j++)
        #pragma unroll
        for (int q = 0; q < 4; q++) oAcc[j][q] = 0.f;
    float m0 = -1e30f, m1 = -1e30f, l0 = 0.f, l1 = 0.f;

    // ldmatrix lane offsets
    const int mi   = lane >> 3;
    const int fRow = ((mi >> 1) * 8) + (lane & 7);   // B-frag row within pair
    const int fCw  = (mi & 1) * 4;
    const int pRowL = wid * 16 + (lane & 15);        // P A-frag
    const int pCwL  = (lane >> 4) * 4;
    unsigned* Ps = smw + POFF;
    const int pr0 = (wid * 16 + lr) * AS2_STR;
    const int pr1 = pr0 + 8 * AS2_STR;

    const int nT = S_LEN / 64;
    issue(0); CP_COMMIT();
    issue(1); CP_COMMIT();

    for (int t = 0; t < nT; t++) {
        CP_WAIT1();
        __syncthreads();
        const int s = t % 3;
        const uint32_t kBase = sb + KOFF(s) * 4;
        const uint32_t vBase = sb + VOFF(s) * 4;

        // S = Q @ K^T
        float sAcc[8][4];
        #pragma unroll
        for (int j = 0; j < 8; j++)
            sAcc[j][0] = sAcc[j][1] = sAcc[j][2] = sAcc[j][3] = 0.f;
        #pragma unroll
        for (int kk = 0; kk < 8; kk++) {
            #pragma unroll
            for (int p = 0; p < 4; p++) {
                unsigned bf[4];
                LDSM_X4(bf[0], bf[1], bf[2], bf[3],
                        kBase + ((16 * p + fRow) * AS2_STR + fCw + 8 * kk) * 4);
                mma_tf32(sAcc[2 * p],     Qf[kk], bf[0], bf[1]);
                mma_tf32(sAcc[2 * p + 1], Qf[kk], bf[2], bf[3]);
            }
        }

        // online softmax
        float mx0 = -1e30f, mx1 = -1e30f;
        #pragma unroll
        for (int j = 0; j < 8; j++) {
            mx0 = fmaxf(mx0, fmaxf(sAcc[j][0], sAcc[j][1]));
            mx1 = fmaxf(mx1, fmaxf(sAcc[j][2], sAcc[j][3]));
        }
        mx0 = fmaxf(mx0, __shfl_xor_sync(0xffffffffu, mx0, 1));
        mx0 = fmaxf(mx0, __shfl_xor_sync(0xffffffffu, mx0, 2));
        mx1 = fmaxf(mx1, __shfl_xor_sync(0xffffffffu, mx1, 1));
        mx1 = fmaxf(mx1, __shfl_xor_sync(0xffffffffu, mx1, 2));

        const float mn0 = fmaxf(m0, mx0), mn1 = fmaxf(m1, mx1);
        const float cor0 = __expf(m0 - mn0), cor1 = __expf(m1 - mn1);
        m0 = mn0; m1 = mn1;

        float s0 = 0.f, s1 = 0.f;
        #pragma unroll
        for (int j = 0; j < 8; j++) {
            sAcc[j][0] = __expf(sAcc[j][0] - mn0); s0 += sAcc[j][0];
            sAcc[j][1] = __expf(sAcc[j][1] - mn0); s0 += sAcc[j][1];
            sAcc[j][2] = __expf(sAcc[j][2] - mn1); s1 += sAcc[j][2];
            sAcc[j][3] = __expf(sAcc[j][3] - mn1); s1 += sAcc[j][3];
        }
        s0 += __shfl_xor_sync(0xffffffffu, s0, 1);
        s0 += __shfl_xor_sync(0xffffffffu, s0, 2);
        s1 += __shfl_xor_sync(0xffffffffu, s1, 1);
        s1 += __shfl_xor_sync(0xffffffffu, s1, 2);
        l0 = l0 * cor0 + s0;
        l1 = l1 * cor1 + s1;

        #pragma unroll
        for (int j = 0; j < 8; j++) {
            oAcc[j][0] *= cor0; oAcc[j][1] *= cor0;
            oAcc[j][2] *= cor1; oAcc[j][3] *= cor1;
        }

        // P -> smem (warp-private rows, rounded)
        #pragma unroll
        for (int j = 0; j < 8; j++) {
            const int colo = 8 * j + 2 * lc;
            *(uint2*)(Ps + pr0 + colo) = make_uint2(f2tf(sAcc[j][0]), f2tf(sAcc[j][1]));
            *(uint2*)(Ps + pr1 + colo) = make_uint2(f2tf(sAcc[j][2]), f2tf(sAcc[j][3]));
        }
        __syncwarp();

        // O += P @ V   (V^T in smem: rows = d, k-contiguous keys)
        #pragma unroll
        for (int kk = 0; kk < 8; kk++) {
            unsigned pf[4];
            LDSM_X4(pf[0], pf[1], pf[2], pf[3],
                    sb + (POFF + pRowL * AS2_STR + pCwL + 8 * kk) * 4);
            #pragma unroll
            for (int p = 0; p < 4; p++) {
                unsigned bf[4];
                LDSM_X4(bf[0], bf[1], bf[2], bf[3],
                        vBase + ((16 * p + fRow) * AS2_STR + fCw + 8 * kk) * 4);
                mma_tf32(oAcc[2 * p],     pf, bf[0], bf[1]);
                mma_tf32(oAcc[2 * p + 1], pf, bf[2], bf[3]);
            }
        }

        if (t + 2 < nT) issue(t + 2);
        CP_COMMIT();
    }

    // epilogue: normalize, round, store head-interleaved ctx
    const float inv0 = 1.f / l0, inv1 = 1.f / l1;
    float* orow0 = g_ctx + (size_t)(b * S_LEN + q0 + wid * 16 + lr) * D_MODEL + h * DK;
    float* orow1 = orow0 + (size_t)8 * D_MODEL;
    #pragma unroll
    for (int j = 0; j < 8; j++) {
        const int colo = 8 * j + 2 * lc;
        *(float2*)(orow0 + colo) =
            make_float2(f2tf_f(oAcc[j][0] * inv0), f2tf_f(oAcc[j][1] * inv0));
        *(float2*)(orow1 + colo) =
            make_float2(f2tf_f(oAcc[j][2] * inv1), f2tf_f(oAcc[j][3] * inv1));
    }
}

// ---------------------------------------------------------------------------
extern "C" void kernel_launch(void* const* d_in, const int* in_sizes, int n_in,
                              void* d_out, int out_size)
{
    (void)in_sizes; (void)n_in; (void)out_size;
    const float* x     = (const float*)d_in[0];
    const float* W_qkv = (const float*)d_in[1];
    const float* b_qkv = (const float*)d_in[2];
    const float* W_o   = (const float*)d_in[3];
    const float* b_o   = (const float*)d_in[4];
    float* out = (float*)d_out;

    static float *p_qkv = nullptr, *p_ctx, *p_xr, *p_wqt, *p_wot;
    if (!p_qkv) {
        cudaGetSymbolAddress((void**)&p_qkv, g_qkv);
        cudaGetSymbolAddress((void**)&p_ctx, g_ctx);
        cudaGetSymbolAddress((void**)&p_xr,  g_xr);
        cudaGetSymbolAddress((void**)&p_wqt, g_wqt);
        cudaGetSymbolAddress((void**)&p_wot, g_wot);
        cudaFuncSetAttribute(k_gemm<true>,
                             cudaFuncAttributeMaxDynamicSharedMemorySize, GT_SMEM);
        cudaFuncSetAttribute(k_gemm<false>,
                             cudaFuncAttributeMaxDynamicSharedMemorySize, GT_SMEM);
        cudaFuncSetAttribute(k_attn,
                             cudaFuncAttributeMaxDynamicSharedMemorySize, AT_SMEM);
    }

    // one-time prep: round x; round+transpose weights
    k_round4<<<(M_ROWS * D_MODEL / 4 + 255) / 256, 256>>>(x, p_xr, M_ROWS * D_MODEL / 4);
    k_trT<<<dim3(QKV_N / 32, D_MODEL / 32), dim3(32, 8)>>>(W_qkv, p_wqt, D_MODEL, QKV_N);
    k_trT<<<dim3(D_MODEL / 32, D_MODEL / 32), dim3(32, 8)>>>(W_o, p_wot, D_MODEL, D_MODEL);

    k_gemm<true><<<dim3(QKV_N / 128, M_ROWS / 128), 256, GT_SMEM>>>(
        p_xr, p_wqt, b_qkv, p_qkv, QKV_N, D_MODEL);
    k_vtrans<<<dim3(S_LEN / 32, DK / 32, B_SZ * NHEADS), dim3(32, 8)>>>();
    k_attn<<<dim3(B_SZ * NHEADS, S_LEN / 128), 256, AT_SMEM>>>();
    k_gemm<false><<<dim3(D_MODEL / 128, M_ROWS / 128), 256, GT_SMEM>>>(
        p_ctx, p_wot, b_o, out, D_MODEL, D_MODEL);
}

// round 9
// speedup vs baseline: 2.0795x; 2.0795x over previous
#include <cuda_runtime.h>
#include <cuda_fp16.h>
#include <cstdint>

#define B_SZ    2
#define S_LEN   2048
#define D_MODEL 1024
#define NHEADS  16
#define DK      64
#define M_ROWS  (B_SZ * S_LEN)     // 4096
#define QKV_N   (3 * D_MODEL)      // 3072

// Scratch (alloc-free: __device__ globals), all fp16 operands
__device__ __half g_qkv[(size_t)M_ROWS * QKV_N];     // qkv (token-major)
__device__ __half g_ctx[(size_t)M_ROWS * D_MODEL];   // ctx head-interleaved
__device__ __half g_xh [(size_t)M_ROWS * D_MODEL];   // x -> half
__device__ __half g_wqt[(size_t)QKV_N * D_MODEL];    // W_qkv^T [N][K] half
__device__ __half g_wot[(size_t)D_MODEL * D_MODEL];  // W_o^T  [N][K] half
__device__ __half g_vt [(size_t)B_SZ * NHEADS * DK * S_LEN]; // V^T per (b,h): [dk][seq]

// ---------------------------------------------------------------------------
// helpers
// ---------------------------------------------------------------------------
__device__ __forceinline__ uint32_t smem_u32(const void* p) {
    uint32_t a;
    asm("{ .reg .u64 t; cvta.to.shared.u64 t, %1; cvt.u32.u64 %0, t; }"
        : "=r"(a) : "l"(p));
    return a;
}

#define CP_ASYNC16(dst, src) \
    asm volatile("cp.async.cg.shared.global [%0], [%1], 16;" :: "r"(dst), "l"(src))
#define CP_COMMIT() asm volatile("cp.async.commit_group;" ::: "memory")
#define CP_WAIT1()  asm volatile("cp.async.wait_group 1;" ::: "memory")

#define LDSM_X4(r0, r1, r2, r3, addr) \
    asm volatile("ldmatrix.sync.aligned.m8n8.x4.shared.b16 {%0,%1,%2,%3}, [%4];" \
                 : "=r"(r0), "=r"(r1), "=r"(r2), "=r"(r3) : "r"(addr))

// D(f32) += A(f16) * B(f16): m16n8k16
__device__ __forceinline__ void mma_f16(float* c, const unsigned* a,
                                        unsigned b0, unsigned b1) {
    asm volatile(
        "mma.sync.aligned.m16n8k16.row.col.f32.f16.f16.f32 "
        "{%0,%1,%2,%3}, {%4,%5,%6,%7}, {%8,%9}, {%0,%1,%2,%3};\n"
        : "+f"(c[0]), "+f"(c[1]), "+f"(c[2]), "+f"(c[3])
        : "r"(a[0]), "r"(a[1]), "r"(a[2]), "r"(a[3]), "r"(b0), "r"(b1));
}

__device__ __forceinline__ unsigned h2u(__half2 h) {
    return *reinterpret_cast<unsigned*>(&h);
}

// ---------------------------------------------------------------------------
// prep kernels
// ---------------------------------------------------------------------------
__global__ void __launch_bounds__(256)
k_h4(const float* __restrict__ in, __half* __restrict__ out, int n4)
{
    int i = blockIdx.x * 256 + threadIdx.x;
    if (i < n4) {
        float4 v = ((const float4*)in)[i];
        ((__half2*)out)[2 * i]     = __floats2half2_rn(v.x, v.y);
        ((__half2*)out)[2 * i + 1] = __floats2half2_rn(v.z, v.w);
    }
}

// transpose+convert: in f32 [R][C] -> out half [C][R]
__global__ void __launch_bounds__(256)
k_trT(const float* __restrict__ in, __half* __restrict__ out, int R, int C)
{
    __shared__ float tile[32][33];
    const int tx = threadIdx.x, ty = threadIdx.y;
    const int c0 = blockIdx.x * 32, r0 = blockIdx.y * 32;
    #pragma unroll
    for (int i = 0; i < 32; i += 8)
        tile[ty + i][tx] = in[(size_t)(r0 + ty + i) * C + c0 + tx];
    __syncthreads();
    #pragma unroll
    for (int i = 0; i < 32; i += 8)
        out[(size_t)(c0 + ty + i) * R + r0 + tx] = __float2half_rn(tile[tx][ty + i]);
}

// V transpose: g_qkv V-slices (half, token-major) -> g_vt half [(bh*64+d)][token]
__global__ void __launch_bounds__(256)
k_vtrans()
{
    __shared__ __half tile[32][34];
    const int tx = threadIdx.x, ty = threadIdx.y;
    const int t0 = blockIdx.x * 32;          // token tile
    const int d0 = blockIdx.y * 32;          // d tile (0 or 32)
    const int bh = blockIdx.z;               // 0..31
    const int b = bh >> 4, h = bh & 15;
    const __half* src = g_qkv + (size_t)b * S_LEN * QKV_N + h * 192 + 128;
    #pragma unroll
    for (int i = 0; i < 32; i += 8)
        tile[ty + i][tx] = src[(size_t)(t0 + ty + i) * QKV_N + d0 + tx];
    __syncthreads();
    __half* dst = g_vt + ((size_t)bh * DK + d0) * S_LEN + t0;
    #pragma unroll
    for (int i = 0; i < 32; i += 8)
        dst[(size_t)(ty + i) * S_LEN + tx] = tile[tx][ty + i];
}

// ---------------------------------------------------------------------------
// FP16 GEMM: C[M,N] = A[M,K] @ BT[N,K]^T + bias[N]
// Block 128x128, BK=32, 3-stage cp.async, 256 threads = 8 warps (4M x 2N),
// warp tile 32x64, mma m16n8k16. smem rows k-contiguous, stride 40 halfs
// (80B: ldmatrix 8-row phases hit 8 distinct 16B banks). 2 CTAs/SM.
// ---------------------------------------------------------------------------
#define HS 40
#define STG_H (128 * HS)                 // halfs per operand per stage: 5120
#define ABUF(s) ((s) * 2 * STG_H)
#define BBUF(s) ((s) * 2 * STG_H + STG_H)
#define GT_SMEM (3 * 2 * STG_H * 2)      // 61440 B

template <bool HALF_OUT>
__global__ void __launch_bounds__(256, 2)
k_gemm(const __half* __restrict__ A, const __half* __restrict__ BT,
       const float* __restrict__ bias, void* __restrict__ Cv,
       int N, int K)
{
    extern __shared__ __half smh[];
    const uint32_t sb = smem_u32(smh);
    const int tid  = threadIdx.x;
    const int wid  = tid >> 5;
    const int lane = tid & 31;
    const int lr   = lane >> 2;
    const int lc   = lane & 3;
    const int wm   = (wid & 3) * 32;
    const int wn   = (wid >> 2) * 64;
    const int bm   = blockIdx.y * 128;
    const int bn   = blockIdx.x * 128;

    float acc[2][8][4];
    #pragma unroll
    for (int i = 0; i < 2; i++)
        #pragma unroll
        for (int j = 0; j < 8; j++)
            #pragma unroll
            for (int q = 0; q < 4; q++) acc[i][j][q] = 0.f;

    // cp.async: 512 16B-chunks per operand per stage -> 2 per thread each
    const int ldRow = tid >> 1;            // 0..127
    const int ldCol = (tid & 1) * 16;      // half col 0 or 16

    auto issue = [&](int t) {
        const int s  = t % 3;
        const int k0 = t * 32;
        const __half* ap = A  + (size_t)(bm + ldRow) * K + k0 + ldCol;
        const __half* bp = BT + (size_t)(bn + ldRow) * K + k0 + ldCol;
        const uint32_t da = sb + (ABUF(s) + ldRow * HS + ldCol) * 2;
        const uint32_t db = sb + (BBUF(s) + ldRow * HS + ldCol) * 2;
        CP_ASYNC16(da,      ap);
        CP_ASYNC16(da + 16, ap + 8);
        CP_ASYNC16(db,      bp);
        CP_ASYNC16(db + 16, bp + 8);
    };

    // ldmatrix lane addressing (shared by A and B x4 pattern)
    const int lane16 = lane & 15;
    const int lhi    = (lane >> 4) * 8;    // +8 halfs for second k-chunk

    const int nT = K / 32;
    issue(0); CP_COMMIT();
    issue(1); CP_COMMIT();

    for (int t = 0; t < nT; t++) {
        CP_WAIT1();
        __syncthreads();
        const int s = t % 3;
        const uint32_t aBase = sb + ABUF(s) * 2;
        const uint32_t bBase = sb + BBUF(s) * 2;

        #pragma unroll
        for (int kk = 0; kk < 2; kk++) {      // two k16 steps
            unsigned af0[4], af1[4];
            LDSM_X4(af0[0], af0[1], af0[2], af0[3],
                    aBase + ((wm + lane16) * HS + lhi + 16 * kk) * 2);
            LDSM_X4(af1[0], af1[1], af1[2], af1[3],
                    aBase + ((wm + 16 + lane16) * HS + lhi + 16 * kk) * 2);
            #pragma unroll
            for (int p = 0; p < 4; p++) {     // 16-n groups
                unsigned bf[4];
                LDSM_X4(bf[0], bf[1], bf[2], bf[3],
                        bBase + ((wn + 16 * p + lane16) * HS + lhi + 16 * kk) * 2);
                mma_f16(acc[0][2 * p],     af0, bf[0], bf[2]);
                mma_f16(acc[1][2 * p],     af1, bf[0], bf[2]);
                mma_f16(acc[0][2 * p + 1], af0, bf[1], bf[3]);
                mma_f16(acc[1][2 * p + 1], af1, bf[1], bf[3]);
            }
        }
        if (t + 2 < nT) issue(t + 2);
        CP_COMMIT();
    }

    #pragma unroll
    for (int j = 0; j < 8; j++) {
        const int col = bn + wn + 8 * j + 2 * lc;
        const float bs0 = bias[col], bs1 = bias[col + 1];
        #pragma unroll
        for (int i = 0; i < 2; i++) {
            const int row = bm + wm + 16 * i + lr;
            if (HALF_OUT) {
                __half* Ch = (__half*)Cv;
                *(__half2*)(Ch + (size_t)row * N + col) =
                    __floats2half2_rn(acc[i][j][0] + bs0, acc[i][j][1] + bs1);
                *(__half2*)(Ch + (size_t)(row + 8) * N + col) =
                    __floats2half2_rn(acc[i][j][2] + bs0, acc[i][j][3] + bs1);
            } else {
                float* Cf = (float*)Cv;
                *(float2*)(Cf + (size_t)row * N + col) =
                    make_float2(acc[i][j][0] + bs0, acc[i][j][1] + bs1);
                *(float2*)(Cf + (size_t)(row + 8) * N + col) =
                    make_float2(acc[i][j][2] + bs0, acc[i][j][3] + bs1);
            }
        }
    }
}

// ---------------------------------------------------------------------------
// FP16 flash attention: 256 threads (8 warps) = 128 q-rows, 64-key tiles,
// 3-stage cp.async for K [keys][dk] and V^T [dk][keys] (both half).
// mma m16n8k16; P converted to half (warp-private smem rows) for PV.
// Stride 72 halfs (144B: ldmatrix conflict-free).
// ---------------------------------------------------------------------------
#define AHS 72
#define KSTG (64 * AHS)                            // 4608 halfs
#define KOFF(s) ((s) * 2 * KSTG)
#define VOFF(s) ((s) * 2 * KSTG + KSTG)
#define POFF    (3 * 2 * KSTG)                     // 27648 halfs
#define AT_SMEM ((POFF + 128 * AHS) * 2)           // 73728 B

__global__ void __launch_bounds__(256, 1)
k_attn()
{
    extern __shared__ __half smh[];
    const uint32_t sb = smem_u32(smh);
    const int tid  = threadIdx.x;
    const int wid  = tid >> 5;
    const int lane = tid & 31;
    const int lr   = lane >> 2;
    const int lc   = lane & 3;
    const int bh   = blockIdx.x;
    const int b    = bh >> 4;
    const int h    = bh & 15;
    const int q0   = blockIdx.y * 128;

    const __half* base = g_qkv + (size_t)b * S_LEN * QKV_N;
    const __half* vtb  = g_vt + (size_t)bh * DK * S_LEN;
    const int ho = h * (3 * DK);

    // Q fragments from gmem, x0.125 (exact pow2 in fp16)
    unsigned Qf[4][4];
    {
        const __half2 scl = __float2half2_rn(0.125f);
        const __half* qr0 = base + (size_t)(q0 + wid * 16 + lr) * QKV_N + ho;
        const __half* qr1 = qr0 + (size_t)8 * QKV_N;
        #pragma unroll
        for (int kk = 0; kk < 4; kk++) {
            Qf[kk][0] = h2u(__hmul2(*(const __half2*)(qr0 + 16 * kk + 2 * lc), scl));
            Qf[kk][1] = h2u(__hmul2(*(const __half2*)(qr1 + 16 * kk + 2 * lc), scl));
            Qf[kk][2] = h2u(__hmul2(*(const __half2*)(qr0 + 16 * kk + 2 * lc + 8), scl));
            Qf[kk][3] = h2u(__hmul2(*(const __half2*)(qr1 + 16 * kk + 2 * lc + 8), scl));
        }
    }

    // cp.async: K and V^T each 64 rows x 8 chunks (512); 2 chunks/thread each
    auto issue = [&](int t) {
        const int s  = t % 3;
        const int r  = tid >> 2;            // row 0..63
        const int cb = (tid & 3) * 16;      // half col 0/16/32/48
        {   // K tile: rows = keys, cols = dims
            const __half* kp = base + (size_t)(t * 64 + r) * QKV_N + ho + DK + cb;
            const uint32_t dk_ = sb + (KOFF(s) + r * AHS + cb) * 2;
            CP_ASYNC16(dk_,      kp);
            CP_ASYNC16(dk_ + 16, kp + 8);
        }
        {   // V^T tile: rows = dims, cols = keys
            const __half* vp = vtb + (size_t)r * S_LEN + t * 64 + cb;
            const uint32_t dv = sb + (VOFF(s) + r * AHS + cb) * 2;
            CP_ASYNC16(dv,      vp);
            CP_ASYNC16(dv + 16, vp + 8);
        }
    };

    float oAcc[8][4];
    #pragma unroll
    for (int j = 0; j < 8; j++)
        #pragma unroll
        for (int q = 0; q < 4; q++) oAcc[j][q] = 0.f;
    float m0 = -1e30f, m1 = -1e30f, l0 = 0.f, l1 = 0.f;

    const int lane16 = lane & 15;
    const int lhi    = (lane >> 4) * 8;
    const int prow   = wid * 16;

    const int nT = S_LEN / 64;
    issue(0); CP_COMMIT();
    issue(1); CP_COMMIT();

    for (int t = 0; t < nT; t++) {
        CP_WAIT1();
        __syncthreads();
        const int s = t % 3;
        const uint32_t kBase = sb + KOFF(s) * 2;
        const uint32_t vBase = sb + VOFF(s) * 2;

        // S = Q @ K^T  (16 q x 64 keys per warp)
        float sAcc[8][4];
        #pragma unroll
        for (int j = 0; j < 8; j++)
            sAcc[j][0] = sAcc[j][1] = sAcc[j][2] = sAcc[j][3] = 0.f;
        #pragma unroll
        for (int kk = 0; kk < 4; kk++) {
            #pragma unroll
            for (int p = 0; p < 4; p++) {
                unsigned bf[4];
                LDSM_X4(bf[0], bf[1], bf[2], bf[3],
                        kBase + ((16 * p + lane16) * AHS + lhi + 16 * kk) * 2);
                mma_f16(sAcc[2 * p],     Qf[kk], bf[0], bf[2]);
                mma_f16(sAcc[2 * p + 1], Qf[kk], bf[1], bf[3]);
            }
        }

        // online softmax (rows lr and lr+8)
        float mx0 = -1e30f, mx1 = -1e30f;
        #pragma unroll
        for (int j = 0; j < 8; j++) {
            mx0 = fmaxf(mx0, fmaxf(sAcc[j][0], sAcc[j][1]));
            mx1 = fmaxf(mx1, fmaxf(sAcc[j][2], sAcc[j][3]));
        }
        mx0 = fmaxf(mx0, __shfl_xor_sync(0xffffffffu, mx0, 1));
        mx0 = fmaxf(mx0, __shfl_xor_sync(0xffffffffu, mx0, 2));
        mx1 = fmaxf(mx1, __shfl_xor_sync(0xffffffffu, mx1, 1));
        mx1 = fmaxf(mx1, __shfl_xor_sync(0xffffffffu, mx1, 2));

        const float mn0 = fmaxf(m0, mx0), mn1 = fmaxf(m1, mx1);
        const float cor0 = __expf(m0 - mn0), cor1 = __expf(m1 - mn1);
        m0 = mn0; m1 = mn1;

        float s0 = 0.f, s1 = 0.f;
        #pragma unroll
        for (int j = 0; j < 8; j++) {
            sAcc[j][0] = __expf(sAcc[j][0] - mn0); s0 += sAcc[j][0];
            sAcc[j][1] = __expf(sAcc[j][1] - mn0); s0 += sAcc[j][1];
            sAcc[j][2] = __expf(sAcc[j][2] - mn1); s1 += sAcc[j][2];
            sAcc[j][3] = __expf(sAcc[j][3] - mn1); s1 += sAcc[j][3];
        }
        s0 += __shfl_xor_sync(0xffffffffu, s0, 1);
        s0 += __shfl_xor_sync(0xffffffffu, s0, 2);
        s1 += __shfl_xor_sync(0xffffffffu, s1, 1);
        s1 += __shfl_xor_sync(0xffffffffu, s1, 2);
        l0 = l0 * cor0 + s0;
        l1 = l1 * cor1 + s1;

        #pragma unroll
        for (int j = 0; j < 8; j++) {
            oAcc[j][0] *= cor0; oAcc[j][1] *= cor0;
            oAcc[j][2] *= cor1; oAcc[j][3] *= cor1;
        }

        // P -> smem half (warp-private rows)
        __half* Ps = smh + POFF;
        #pragma unroll
        for (int j = 0; j < 8; j++) {
            const int colo = 8 * j + 2 * lc;
            *(__half2*)(Ps + (prow + lr) * AHS + colo) =
                __floats2half2_rn(sAcc[j][0], sAcc[j][1]);
            *(__half2*)(Ps + (prow + 8 + lr) * AHS + colo) =
                __floats2half2_rn(sAcc[j][2], sAcc[j][3]);
        }
        __syncwarp();

        // O += P @ V  (V^T smem: rows = dims, k-contiguous keys)
        #pragma unroll
        for (int kk = 0; kk < 4; kk++) {      // 16-key steps
            unsigned pf[4];
            LDSM_X4(pf[0], pf[1], pf[2], pf[3],
                    sb + (POFF + (prow + lane16) * AHS + lhi + 16 * kk) * 2);
            #pragma unroll
            for (int p = 0; p < 4; p++) {     // 16-d groups
                unsigned bf[4];
                LDSM_X4(bf[0], bf[1], bf[2], bf[3],
                        vBase + ((16 * p + lane16) * AHS + lhi + 16 * kk) * 2);
                mma_f16(oAcc[2 * p],     pf, bf[0], bf[2]);
                mma_f16(oAcc[2 * p + 1], pf, bf[1], bf[3]);
            }
        }

        if (t + 2 < nT) issue(t + 2);
        CP_COMMIT();
    }

    // epilogue: normalize, convert half, store head-interleaved ctx
    const float inv0 = 1.f / l0, inv1 = 1.f / l1;
    __half* orow0 = g_ctx + (size_t)(b * S_LEN + q0 + wid * 16 + lr) * D_MODEL + h * DK;
    __half* orow1 = orow0 + (size_t)8 * D_MODEL;
    #pragma unroll
    for (int j = 0; j < 8; j++) {
        const int colo = 8 * j + 2 * lc;
        *(__half2*)(orow0 + colo) =
            __floats2half2_rn(oAcc[j][0] * inv0, oAcc[j][1] * inv0);
        *(__half2*)(orow1 + colo) =
            __floats2half2_rn(oAcc[j][2] * inv1, oAcc[j][3] * inv1);
    }
}

// ---------------------------------------------------------------------------
extern "C" void kernel_launch(void* const* d_in, const int* in_sizes, int n_in,
                              void* d_out, int out_size)
{
    (void)in_sizes; (void)n_in; (void)out_size;
    const float* x     = (const float*)d_in[0];
    const float* W_qkv = (const float*)d_in[1];
    const float* b_qkv = (const float*)d_in[2];
    const float* W_o   = (const float*)d_in[3];
    const float* b_o   = (const float*)d_in[4];
    float* out = (float*)d_out;

    static __half *p_qkv = nullptr, *p_ctx, *p_xh, *p_wqt, *p_wot;
    if (!p_qkv) {
        cudaGetSymbolAddress((void**)&p_qkv, g_qkv);
        cudaGetSymbolAddress((void**)&p_ctx, g_ctx);
        cudaGetSymbolAddress((void**)&p_xh,  g_xh);
        cudaGetSymbolAddress((void**)&p_wqt, g_wqt);
        cudaGetSymbolAddress((void**)&p_wot, g_wot);
        cudaFuncSetAttribute(k_gemm<true>,
                             cudaFuncAttributeMaxDynamicSharedMemorySize, GT_SMEM);
        cudaFuncSetAttribute(k_gemm<false>,
                             cudaFuncAttributeMaxDynamicSharedMemorySize, GT_SMEM);
        cudaFuncSetAttribute(k_attn,
                             cudaFuncAttributeMaxDynamicSharedMemorySize, AT_SMEM);
    }

    // prep: x -> half; weights -> transposed half
    k_h4<<<(M_ROWS * D_MODEL / 4 + 255) / 256, 256>>>(x, p_xh, M_ROWS * D_MODEL / 4);
    k_trT<<<dim3(QKV_N / 32, D_MODEL / 32), dim3(32, 8)>>>(W_qkv, p_wqt, D_MODEL, QKV_N);
    k_trT<<<dim3(D_MODEL / 32, D_MODEL / 32), dim3(32, 8)>>>(W_o, p_wot, D_MODEL, D_MODEL);

    k_gemm<true><<<dim3(QKV_N / 128, M_ROWS / 128), 256, GT_SMEM>>>(
        p_xh, p_wqt, b_qkv, p_qkv, QKV_N, D_MODEL);
    k_vtrans<<<dim3(S_LEN / 32, DK / 32, B_SZ * NHEADS), dim3(32, 8)>>>();
    k_attn<<<dim3(B_SZ * NHEADS, S_LEN / 128), 256, AT_SMEM>>>();
    k_gemm<false><<<dim3(D_MODEL / 128, M_ROWS / 128), 256, GT_SMEM>>>(
        p_ctx, p_wot, b_o, out, D_MODEL, D_MODEL);
}

// round 10
// speedup vs baseline: 2.2397x; 1.0770x over previous
#include <cuda_runtime.h>
#include <cuda_fp16.h>
#include <cstdint>

#define B_SZ    2
#define S_LEN   2048
#define D_MODEL 1024
#define NHEADS  16
#define DK      64
#define M_ROWS  (B_SZ * S_LEN)     // 4096
#define QKV_N   (3 * D_MODEL)      // 3072

// Scratch (alloc-free: __device__ globals), all fp16 operands
__device__ __half g_qkv[(size_t)M_ROWS * QKV_N];     // qkv (token-major)
__device__ __half g_ctx[(size_t)M_ROWS * D_MODEL];   // ctx head-interleaved
__device__ __half g_xh [(size_t)M_ROWS * D_MODEL];   // x -> half
__device__ __half g_wqt[(size_t)QKV_N * D_MODEL];    // W_qkv^T [N][K] half
__device__ __half g_wot[(size_t)D_MODEL * D_MODEL];  // W_o^T  [N][K] half
__device__ __half g_vt [(size_t)B_SZ * NHEADS * DK * S_LEN]; // V^T per (b,h): [dk][seq]

// ---------------------------------------------------------------------------
// helpers
// ---------------------------------------------------------------------------
__device__ __forceinline__ uint32_t smem_u32(const void* p) {
    uint32_t a;
    asm("{ .reg .u64 t; cvta.to.shared.u64 t, %1; cvt.u32.u64 %0, t; }"
        : "=r"(a) : "l"(p));
    return a;
}

#define CP_ASYNC16(dst, src) \
    asm volatile("cp.async.cg.shared.global [%0], [%1], 16;" :: "r"(dst), "l"(src))
#define CP_COMMIT() asm volatile("cp.async.commit_group;" ::: "memory")
#define CP_WAIT0()  asm volatile("cp.async.wait_group 0;" ::: "memory")
#define CP_WAIT2()  asm volatile("cp.async.wait_group 2;" ::: "memory")

#define LDSM_X4(r0, r1, r2, r3, addr) \
    asm volatile("ldmatrix.sync.aligned.m8n8.x4.shared.b16 {%0,%1,%2,%3}, [%4];" \
                 : "=r"(r0), "=r"(r1), "=r"(r2), "=r"(r3) : "r"(addr))

// D(f32) += A(f16) * B(f16): m16n8k16
__device__ __forceinline__ void mma_f16(float* c, const unsigned* a,
                                        unsigned b0, unsigned b1) {
    asm volatile(
        "mma.sync.aligned.m16n8k16.row.col.f32.f16.f16.f32 "
        "{%0,%1,%2,%3}, {%4,%5,%6,%7}, {%8,%9}, {%0,%1,%2,%3};\n"
        : "+f"(c[0]), "+f"(c[1]), "+f"(c[2]), "+f"(c[3])
        : "r"(a[0]), "r"(a[1]), "r"(a[2]), "r"(a[3]), "r"(b0), "r"(b1));
}

__device__ __forceinline__ unsigned h2u(__half2 h) {
    return *reinterpret_cast<unsigned*>(&h);
}

// ---------------------------------------------------------------------------
// prep kernels
// ---------------------------------------------------------------------------
__global__ void __launch_bounds__(256)
k_h4(const float* __restrict__ in, __half* __restrict__ out, int n4)
{
    int i = blockIdx.x * 256 + threadIdx.x;
    if (i < n4) {
        float4 v = ((const float4*)in)[i];
        ((__half2*)out)[2 * i]     = __floats2half2_rn(v.x, v.y);
        ((__half2*)out)[2 * i + 1] = __floats2half2_rn(v.z, v.w);
    }
}

// transpose+convert: in f32 [R][C] -> out half [C][R]
__global__ void __launch_bounds__(256)
k_trT(const float* __restrict__ in, __half* __restrict__ out, int R, int C)
{
    __shared__ float tile[32][33];
    const int tx = threadIdx.x, ty = threadIdx.y;
    const int c0 = blockIdx.x * 32, r0 = blockIdx.y * 32;
    #pragma unroll
    for (int i = 0; i < 32; i += 8)
        tile[ty + i][tx] = in[(size_t)(r0 + ty + i) * C + c0 + tx];
    __syncthreads();
    #pragma unroll
    for (int i = 0; i < 32; i += 8)
        out[(size_t)(c0 + ty + i) * R + r0 + tx] = __float2half_rn(tile[tx][ty + i]);
}

// V transpose: g_qkv V-slices (half, token-major) -> g_vt half [(bh*64+d)][token]
__global__ void __launch_bounds__(256)
k_vtrans()
{
    __shared__ __half tile[32][34];
    const int tx = threadIdx.x, ty = threadIdx.y;
    const int t0 = blockIdx.x * 32;          // token tile
    const int d0 = blockIdx.y * 32;          // d tile (0 or 32)
    const int bh = blockIdx.z;               // 0..31
    const int b = bh >> 4, h = bh & 15;
    const __half* src = g_qkv + (size_t)b * S_LEN * QKV_N + h * 192 + 128;
    #pragma unroll
    for (int i = 0; i < 32; i += 8)
        tile[ty + i][tx] = src[(size_t)(t0 + ty + i) * QKV_N + d0 + tx];
    __syncthreads();
    __half* dst = g_vt + ((size_t)bh * DK + d0) * S_LEN + t0;
    #pragma unroll
    for (int i = 0; i < 32; i += 8)
        dst[(size_t)(ty + i) * S_LEN + tx] = tile[tx][ty + i];
}

// ---------------------------------------------------------------------------
// FP16 GEMM: C[M,N] = A[M,K] @ BT[N,K]^T + bias[N]
// Block 128x128, BK=32, 4-stage cp.async (wait_group 2), 256 threads =
// 8 warps (4M x 2N), warp tile 32x64, mma m16n8k16. 2 CTAs/SM.
// smem rows k-contiguous, stride 40 halfs.
// ---------------------------------------------------------------------------
#define HS 40
#define STG_H (128 * HS)                 // halfs per operand per stage: 5120
#define ABUF(s) ((s) * 2 * STG_H)
#define BBUF(s) ((s) * 2 * STG_H + STG_H)
#define GT_SMEM (4 * 2 * STG_H * 2)      // 81920 B

template <bool HALF_OUT>
__global__ void __launch_bounds__(256, 2)
k_gemm(const __half* __restrict__ A, const __half* __restrict__ BT,
       const float* __restrict__ bias, void* __restrict__ Cv,
       int N, int K)
{
    extern __shared__ __half smh[];
    const uint32_t sb = smem_u32(smh);
    const int tid  = threadIdx.x;
    const int wid  = tid >> 5;
    const int lane = tid & 31;
    const int lr   = lane >> 2;
    const int lc   = lane & 3;
    const int wm   = (wid & 3) * 32;
    const int wn   = (wid >> 2) * 64;
    const int bm   = blockIdx.y * 128;
    const int bn   = blockIdx.x * 128;

    float acc[2][8][4];
    #pragma unroll
    for (int i = 0; i < 2; i++)
        #pragma unroll
        for (int j = 0; j < 8; j++)
            #pragma unroll
            for (int q = 0; q < 4; q++) acc[i][j][q] = 0.f;

    // cp.async: 512 16B-chunks per operand per stage -> 2 per thread each
    const int ldRow = tid >> 1;            // 0..127
    const int ldCol = (tid & 1) * 16;      // half col 0 or 16

    auto issue = [&](int t) {
        const int s  = t & 3;
        const int k0 = t * 32;
        const __half* ap = A  + (size_t)(bm + ldRow) * K + k0 + ldCol;
        const __half* bp = BT + (size_t)(bn + ldRow) * K + k0 + ldCol;
        const uint32_t da = sb + (ABUF(s) + ldRow * HS + ldCol) * 2;
        const uint32_t db = sb + (BBUF(s) + ldRow * HS + ldCol) * 2;
        CP_ASYNC16(da,      ap);
        CP_ASYNC16(da + 16, ap + 8);
        CP_ASYNC16(db,      bp);
        CP_ASYNC16(db + 16, bp + 8);
    };

    const int lane16 = lane & 15;
    const int lhi    = (lane >> 4) * 8;    // +8 halfs for second k-chunk

    const int nT = K / 32;
    issue(0); CP_COMMIT();
    issue(1); CP_COMMIT();
    issue(2); CP_COMMIT();

    for (int t = 0; t < nT; t++) {
        CP_WAIT2();
        __syncthreads();
        const int s = t & 3;
        const uint32_t aBase = sb + ABUF(s) * 2;
        const uint32_t bBase = sb + BBUF(s) * 2;

        #pragma unroll
        for (int kk = 0; kk < 2; kk++) {      // two k16 steps
            unsigned af0[4], af1[4];
            LDSM_X4(af0[0], af0[1], af0[2], af0[3],
                    aBase + ((wm + lane16) * HS + lhi + 16 * kk) * 2);
            LDSM_X4(af1[0], af1[1], af1[2], af1[3],
                    aBase + ((wm + 16 + lane16) * HS + lhi + 16 * kk) * 2);
            #pragma unroll
            for (int p = 0; p < 4; p++) {     // 16-n groups
                unsigned bf[4];
                LDSM_X4(bf[0], bf[1], bf[2], bf[3],
                        bBase + ((wn + 16 * p + lane16) * HS + lhi + 16 * kk) * 2);
                mma_f16(acc[0][2 * p],     af0, bf[0], bf[2]);
                mma_f16(acc[1][2 * p],     af1, bf[0], bf[2]);
                mma_f16(acc[0][2 * p + 1], af0, bf[1], bf[3]);
                mma_f16(acc[1][2 * p + 1], af1, bf[1], bf[3]);
            }
        }
        if (t + 3 < nT) issue(t + 3);
        CP_COMMIT();
    }

    #pragma unroll
    for (int j = 0; j < 8; j++) {
        const int col = bn + wn + 8 * j + 2 * lc;
        const float bs0 = bias[col], bs1 = bias[col + 1];
        #pragma unroll
        for (int i = 0; i < 2; i++) {
            const int row = bm + wm + 16 * i + lr;
            if (HALF_OUT) {
                __half* Ch = (__half*)Cv;
                *(__half2*)(Ch + (size_t)row * N + col) =
                    __floats2half2_rn(acc[i][j][0] + bs0, acc[i][j][1] + bs1);
                *(__half2*)(Ch + (size_t)(row + 8) * N + col) =
                    __floats2half2_rn(acc[i][j][2] + bs0, acc[i][j][3] + bs1);
            } else {
                float* Cf = (float*)Cv;
                *(float2*)(Cf + (size_t)row * N + col) =
                    make_float2(acc[i][j][0] + bs0, acc[i][j][1] + bs1);
                *(float2*)(Cf + (size_t)(row + 8) * N + col) =
                    make_float2(acc[i][j][2] + bs0, acc[i][j][3] + bs1);
            }
        }
    }
}

// ---------------------------------------------------------------------------
// FP16 flash attention: 256 threads (8 warps) = 128 q-rows, 64-key tiles.
// 2-stage cp.async (issue t+1 right after the top-of-tile sync; wait_group 0)
// -> 55.3KB smem -> 2 CTAs/SM, softmax of one CTA overlaps HMMA of the other.
// mma m16n8k16; P converted to half (warp-private smem rows) for PV.
// ---------------------------------------------------------------------------
#define AHS 72
#define KSTG (64 * AHS)                            // 4608 halfs
#define KOFF(s) ((s) * 2 * KSTG)
#define VOFF(s) ((s) * 2 * KSTG + KSTG)
#define POFF    (2 * 2 * KSTG)                     // 18432 halfs
#define AT_SMEM ((POFF + 128 * AHS) * 2)           // 55296 B

__global__ void __launch_bounds__(256, 2)
k_attn()
{
    extern __shared__ __half smh[];
    const uint32_t sb = smem_u32(smh);
    const int tid  = threadIdx.x;
    const int wid  = tid >> 5;
    const int lane = tid & 31;
    const int lr   = lane >> 2;
    const int lc   = lane & 3;
    const int bh   = blockIdx.x;
    const int b    = bh >> 4;
    const int h    = bh & 15;
    const int q0   = blockIdx.y * 128;

    const __half* base = g_qkv + (size_t)b * S_LEN * QKV_N;
    const __half* vtb  = g_vt + (size_t)bh * DK * S_LEN;
    const int ho = h * (3 * DK);

    // Q fragments from gmem, x0.125 (exact pow2 in fp16)
    unsigned Qf[4][4];
    {
        const __half2 scl = __float2half2_rn(0.125f);
        const __half* qr0 = base + (size_t)(q0 + wid * 16 + lr) * QKV_N + ho;
        const __half* qr1 = qr0 + (size_t)8 * QKV_N;
        #pragma unroll
        for (int kk = 0; kk < 4; kk++) {
            Qf[kk][0] = h2u(__hmul2(*(const __half2*)(qr0 + 16 * kk + 2 * lc), scl));
            Qf[kk][1] = h2u(__hmul2(*(const __half2*)(qr1 + 16 * kk + 2 * lc), scl));
            Qf[kk][2] = h2u(__hmul2(*(const __half2*)(qr0 + 16 * kk + 2 * lc + 8), scl));
            Qf[kk][3] = h2u(__hmul2(*(const __half2*)(qr1 + 16 * kk + 2 * lc + 8), scl));
        }
    }

    // cp.async: K and V^T each 64 rows x 8 chunks (512); 2 chunks/thread each
    auto issue = [&](int t) {
        const int s  = t & 1;
        const int r  = tid >> 2;            // row 0..63
        const int cb = (tid & 3) * 16;      // half col 0/16/32/48
        {   // K tile: rows = keys, cols = dims
            const __half* kp = base + (size_t)(t * 64 + r) * QKV_N + ho + DK + cb;
            const uint32_t dk_ = sb + (KOFF(s) + r * AHS + cb) * 2;
            CP_ASYNC16(dk_,      kp);
            CP_ASYNC16(dk_ + 16, kp + 8);
        }
        {   // V^T tile: rows = dims, cols = keys
            const __half* vp = vtb + (size_t)r * S_LEN + t * 64 + cb;
            const uint32_t dv = sb + (VOFF(s) + r * AHS + cb) * 2;
            CP_ASYNC16(dv,      vp);
            CP_ASYNC16(dv + 16, vp + 8);
        }
    };

    float oAcc[8][4];
    #pragma unroll
    for (int j = 0; j < 8; j++)
        #pragma unroll
        for (int q = 0; q < 4; q++) oAcc[j][q] = 0.f;
    float m0 = -1e30f, m1 = -1e30f, l0 = 0.f, l1 = 0.f;

    const int lane16 = lane & 15;
    const int lhi    = (lane >> 4) * 8;
    const int prow   = wid * 16;

    const int nT = S_LEN / 64;
    issue(0); CP_COMMIT();

    for (int t = 0; t < nT; t++) {
        CP_WAIT0();
        __syncthreads();
        // buffer (t+1)&1 was released by the sync above (compute t-1 done)
        if (t + 1 < nT) issue(t + 1);
        CP_COMMIT();

        const int s = t & 1;
        const uint32_t kBase = sb + KOFF(s) * 2;
        const uint32_t vBase = sb + VOFF(s) * 2;

        // S = Q @ K^T  (16 q x 64 keys per warp)
        float sAcc[8][4];
        #pragma unroll
        for (int j = 0; j < 8; j++)
            sAcc[j][0] = sAcc[j][1] = sAcc[j][2] = sAcc[j][3] = 0.f;
        #pragma unroll
        for (int kk = 0; kk < 4; kk++) {
            #pragma unroll
            for (int p = 0; p < 4; p++) {
                unsigned bf[4];
                LDSM_X4(bf[0], bf[1], bf[2], bf[3],
                        kBase + ((16 * p + lane16) * AHS + lhi + 16 * kk) * 2);
                mma_f16(sAcc[2 * p],     Qf[kk], bf[0], bf[2]);
                mma_f16(sAcc[2 * p + 1], Qf[kk], bf[1], bf[3]);
            }
        }

        // online softmax (rows lr and lr+8)
        float mx0 = -1e30f, mx1 = -1e30f;
        #pragma unroll
        for (int j = 0; j < 8; j++) {
            mx0 = fmaxf(mx0, fmaxf(sAcc[j][0], sAcc[j][1]));
            mx1 = fmaxf(mx1, fmaxf(sAcc[j][2], sAcc[j][3]));
        }
        mx0 = fmaxf(mx0, __shfl_xor_sync(0xffffffffu, mx0, 1));
        mx0 = fmaxf(mx0, __shfl_xor_sync(0xffffffffu, mx0, 2));
        mx1 = fmaxf(mx1, __shfl_xor_sync(0xffffffffu, mx1, 1));
        mx1 = fmaxf(mx1, __shfl_xor_sync(0xffffffffu, mx1, 2));

        const float mn0 = fmaxf(m0, mx0), mn1 = fmaxf(m1, mx1);
        const float cor0 = __expf(m0 - mn0), cor1 = __expf(m1 - mn1);
        m0 = mn0; m1 = mn1;

        float s0 = 0.f, s1 = 0.f;
        #pragma unroll
        for (int j = 0; j < 8; j++) {
            sAcc[j][0] = __expf(sAcc[j][0] - mn0); s0 += sAcc[j][0];
            sAcc[j][1] = __expf(sAcc[j][1] - mn0); s0 += sAcc[j][1];
            sAcc[j][2] = __expf(sAcc[j][2] - mn1); s1 += sAcc[j][2];
            sAcc[j][3] = __expf(sAcc[j][3] - mn1); s1 += sAcc[j][3];
        }
        s0 += __shfl_xor_sync(0xffffffffu, s0, 1);
        s0 += __shfl_xor_sync(0xffffffffu, s0, 2);
        s1 += __shfl_xor_sync(0xffffffffu, s1, 1);
        s1 += __shfl_xor_sync(0xffffffffu, s1, 2);
        l0 = l0 * cor0 + s0;
        l1 = l1 * cor1 + s1;

        #pragma unroll
        for (int j = 0; j < 8; j++) {
            oAcc[j][0] *= cor0; oAcc[j][1] *= cor0;
            oAcc[j][2] *= cor1; oAcc[j][3] *= cor1;
        }

        // P -> smem half (warp-private rows)
        __half* Ps = smh + POFF;
        #pragma unroll
        for (int j = 0; j < 8; j++) {
            const int colo = 8 * j + 2 * lc;
            *(__half2*)(Ps + (prow + lr) * AHS + colo) =
                __floats2half2_rn(sAcc[j][0], sAcc[j][1]);
            *(__half2*)(Ps + (prow + 8 + lr) * AHS + colo) =
                __floats2half2_rn(sAcc[j][2], sAcc[j][3]);
        }
        __syncwarp();

        // O += P @ V  (V^T smem: rows = dims, k-contiguous keys)
        #pragma unroll
        for (int kk = 0; kk < 4; kk++) {      // 16-key steps
            unsigned pf[4];
            LDSM_X4(pf[0], pf[1], pf[2], pf[3],
                    sb + (POFF + (prow + lane16) * AHS + lhi + 16 * kk) * 2);
            #pragma unroll
            for (int p = 0; p < 4; p++) {     // 16-d groups
                unsigned bf[4];
                LDSM_X4(bf[0], bf[1], bf[2], bf[3],
                        vBase + ((16 * p + lane16) * AHS + lhi + 16 * kk) * 2);
                mma_f16(oAcc[2 * p],     pf, bf[0], bf[2]);
                mma_f16(oAcc[2 * p + 1], pf, bf[1], bf[3]);
            }
        }
    }

    // epilogue: normalize, convert half, store head-interleaved ctx
    const float inv0 = 1.f / l0, inv1 = 1.f / l1;
    __half* orow0 = g_ctx + (size_t)(b * S_LEN + q0 + wid * 16 + lr) * D_MODEL + h * DK;
    __half* orow1 = orow0 + (size_t)8 * D_MODEL;
    #pragma unroll
    for (int j = 0; j < 8; j++) {
        const int colo = 8 * j + 2 * lc;
        *(__half2*)(orow0 + colo) =
            __floats2half2_rn(oAcc[j][0] * inv0, oAcc[j][1] * inv0);
        *(__half2*)(orow1 + colo) =
            __floats2half2_rn(oAcc[j][2] * inv1, oAcc[j][3] * inv1);
    }
}

// ---------------------------------------------------------------------------
extern "C" void kernel_launch(void* const* d_in, const int* in_sizes, int n_in,
                              void* d_out, int out_size)
{
    (void)in_sizes; (void)n_in; (void)out_size;
    const float* x     = (const float*)d_in[0];
    const float* W_qkv = (const float*)d_in[1];
    const float* b_qkv = (const float*)d_in[2];
    const float* W_o   = (const float*)d_in[3];
    const float* b_o   = (const float*)d_in[4];
    float* out = (float*)d_out;

    static __half *p_qkv = nullptr, *p_ctx, *p_xh, *p_wqt, *p_wot;
    if (!p_qkv) {
        cudaGetSymbolAddress((void**)&p_qkv, g_qkv);
        cudaGetSymbolAddress((void**)&p_ctx, g_ctx);
        cudaGetSymbolAddress((void**)&p_xh,  g_xh);
        cudaGetSymbolAddress((void**)&p_wqt, g_wqt);
        cudaGetSymbolAddress((void**)&p_wot, g_wot);
        cudaFuncSetAttribute(k_gemm<true>,
                             cudaFuncAttributeMaxDynamicSharedMemorySize, GT_SMEM);
        cudaFuncSetAttribute(k_gemm<false>,
                             cudaFuncAttributeMaxDynamicSharedMemorySize, GT_SMEM);
        cudaFuncSetAttribute(k_attn,
                             cudaFuncAttributeMaxDynamicSharedMemorySize, AT_SMEM);
    }

    // prep: x -> half; weights -> transposed half
    k_h4<<<(M_ROWS * D_MODEL / 4 + 255) / 256, 256>>>(x, p_xh, M_ROWS * D_MODEL / 4);
    k_trT<<<dim3(QKV_N / 32, D_MODEL / 32), dim3(32, 8)>>>(W_qkv, p_wqt, D_MODEL, QKV_N);
    k_trT<<<dim3(D_MODEL / 32, D_MODEL / 32), dim3(32, 8)>>>(W_o, p_wot, D_MODEL, D_MODEL);

    k_gemm<true><<<dim3(QKV_N / 128, M_ROWS / 128), 256, GT_SMEM>>>(
        p_xh, p_wqt, b_qkv, p_qkv, QKV_N, D_MODEL);
    k_vtrans<<<dim3(S_LEN / 32, DK / 32, B_SZ * NHEADS), dim3(32, 8)>>>();
    k_attn<<<dim3(B_SZ * NHEADS, S_LEN / 128), 256, AT_SMEM>>>();
    k_gemm<false><<<dim3(D_MODEL / 128, M_ROWS / 128), 256, GT_SMEM>>>(
        p_ctx, p_wot, b_o, out, D_MODEL, D_MODEL);
}

// round 11
// speedup vs baseline: 2.3426x; 1.0459x over previous
#include <cuda_runtime.h>
#include <cuda_fp16.h>
#include <cstdint>

#define B_SZ    2
#define S_LEN   2048
#define D_MODEL 1024
#define NHEADS  16
#define DK      64
#define M_ROWS  (B_SZ * S_LEN)     // 4096
#define QKV_N   (3 * D_MODEL)      // 3072

// Scratch (alloc-free: __device__ globals), all fp16 operands
__device__ __half g_qkv[(size_t)M_ROWS * QKV_N];     // qkv (token-major)
__device__ __half g_ctx[(size_t)M_ROWS * D_MODEL];   // ctx head-interleaved
__device__ __half g_xh [(size_t)M_ROWS * D_MODEL];   // x -> half
__device__ __half g_wqt[(size_t)QKV_N * D_MODEL];    // W_qkv^T [N][K] half
__device__ __half g_wot[(size_t)D_MODEL * D_MODEL];  // W_o^T  [N][K] half
__device__ __half g_vt [(size_t)B_SZ * NHEADS * DK * S_LEN]; // V^T per (b,h): [dk][seq]

// ---------------------------------------------------------------------------
// helpers
// ---------------------------------------------------------------------------
__device__ __forceinline__ uint32_t smem_u32(const void* p) {
    uint32_t a;
    asm("{ .reg .u64 t; cvta.to.shared.u64 t, %1; cvt.u32.u64 %0, t; }"
        : "=r"(a) : "l"(p));
    return a;
}

#define CP_ASYNC16(dst, src) \
    asm volatile("cp.async.cg.shared.global [%0], [%1], 16;" :: "r"(dst), "l"(src))
#define CP_COMMIT() asm volatile("cp.async.commit_group;" ::: "memory")
#define CP_WAIT0()  asm volatile("cp.async.wait_group 0;" ::: "memory")
#define CP_WAIT2()  asm volatile("cp.async.wait_group 2;" ::: "memory")

#define LDSM_X4(r0, r1, r2, r3, addr) \
    asm volatile("ldmatrix.sync.aligned.m8n8.x4.shared.b16 {%0,%1,%2,%3}, [%4];" \
                 : "=r"(r0), "=r"(r1), "=r"(r2), "=r"(r3) : "r"(addr))

// D(f32) += A(f16) * B(f16): m16n8k16
__device__ __forceinline__ void mma_f16(float* c, const unsigned* a,
                                        unsigned b0, unsigned b1) {
    asm volatile(
        "mma.sync.aligned.m16n8k16.row.col.f32.f16.f16.f32 "
        "{%0,%1,%2,%3}, {%4,%5,%6,%7}, {%8,%9}, {%0,%1,%2,%3};\n"
        : "+f"(c[0]), "+f"(c[1]), "+f"(c[2]), "+f"(c[3])
        : "r"(a[0]), "r"(a[1]), "r"(a[2]), "r"(a[3]), "r"(b0), "r"(b1));
}

__device__ __forceinline__ unsigned h2u(__half2 h) {
    return *reinterpret_cast<unsigned*>(&h);
}

// ---------------------------------------------------------------------------
// prep kernels
// ---------------------------------------------------------------------------
__global__ void __launch_bounds__(256)
k_h4(const float* __restrict__ in, __half* __restrict__ out, int n4)
{
    int i = blockIdx.x * 256 + threadIdx.x;
    if (i < n4) {
        float4 v = ((const float4*)in)[i];
        ((__half2*)out)[2 * i]     = __floats2half2_rn(v.x, v.y);
        ((__half2*)out)[2 * i + 1] = __floats2half2_rn(v.z, v.w);
    }
}

// transpose+convert: in f32 [R][C] -> out half [C][R]
__global__ void __launch_bounds__(256)
k_trT(const float* __restrict__ in, __half* __restrict__ out, int R, int C)
{
    __shared__ float tile[32][33];
    const int tx = threadIdx.x, ty = threadIdx.y;
    const int c0 = blockIdx.x * 32, r0 = blockIdx.y * 32;
    #pragma unroll
    for (int i = 0; i < 32; i += 8)
        tile[ty + i][tx] = in[(size_t)(r0 + ty + i) * C + c0 + tx];
    __syncthreads();
    #pragma unroll
    for (int i = 0; i < 32; i += 8)
        out[(size_t)(c0 + ty + i) * R + r0 + tx] = __float2half_rn(tile[tx][ty + i]);
}

// V transpose: g_qkv V-slices (half, token-major) -> g_vt half [(bh*64+d)][token]
__global__ void __launch_bounds__(256)
k_vtrans()
{
    __shared__ __half tile[32][34];
    const int tx = threadIdx.x, ty = threadIdx.y;
    const int t0 = blockIdx.x * 32;          // token tile
    const int d0 = blockIdx.y * 32;          // d tile (0 or 32)
    const int bh = blockIdx.z;               // 0..31
    const int b = bh >> 4, h = bh & 15;
    const __half* src = g_qkv + (size_t)b * S_LEN * QKV_N + h * 192 + 128;
    #pragma unroll
    for (int i = 0; i < 32; i += 8)
        tile[ty + i][tx] = src[(size_t)(t0 + ty + i) * QKV_N + d0 + tx];
    __syncthreads();
    __half* dst = g_vt + ((size_t)bh * DK + d0) * S_LEN + t0;
    #pragma unroll
    for (int i = 0; i < 32; i += 8)
        dst[(size_t)(ty + i) * S_LEN + tx] = tile[tx][ty + i];
}

// ---------------------------------------------------------------------------
// FP16 GEMM: C[M,N] = A[M,K] @ BT[N,K]^T + bias[N]
// Block 128x128, BK=32, 4-stage cp.async (wait_group 2), 256 threads =
// 8 warps (4M x 2N), warp tile 32x64, mma m16n8k16. 2 CTAs/SM.
// smem rows k-contiguous, stride 40 halfs.
// ---------------------------------------------------------------------------
#define HS 40
#define STG_H (128 * HS)                 // halfs per operand per stage: 5120
#define ABUF(s) ((s) * 2 * STG_H)
#define BBUF(s) ((s) * 2 * STG_H + STG_H)
#define GT_SMEM (4 * 2 * STG_H * 2)      // 81920 B

template <bool HALF_OUT>
__global__ void __launch_bounds__(256, 2)
k_gemm(const __half* __restrict__ A, const __half* __restrict__ BT,
       const float* __restrict__ bias, void* __restrict__ Cv,
       int N, int K)
{
    extern __shared__ __half smh[];
    const uint32_t sb = smem_u32(smh);
    const int tid  = threadIdx.x;
    const int wid  = tid >> 5;
    const int lane = tid & 31;
    const int lr   = lane >> 2;
    const int lc   = lane & 3;
    const int wm   = (wid & 3) * 32;
    const int wn   = (wid >> 2) * 64;
    const int bm   = blockIdx.y * 128;
    const int bn   = blockIdx.x * 128;

    float acc[2][8][4];
    #pragma unroll
    for (int i = 0; i < 2; i++)
        #pragma unroll
        for (int j = 0; j < 8; j++)
            #pragma unroll
            for (int q = 0; q < 4; q++) acc[i][j][q] = 0.f;

    // cp.async: 512 16B-chunks per operand per stage -> 2 per thread each
    const int ldRow = tid >> 1;            // 0..127
    const int ldCol = (tid & 1) * 16;      // half col 0 or 16

    auto issue = [&](int t) {
        const int s  = t & 3;
        const int k0 = t * 32;
        const __half* ap = A  + (size_t)(bm + ldRow) * K + k0 + ldCol;
        const __half* bp = BT + (size_t)(bn + ldRow) * K + k0 + ldCol;
        const uint32_t da = sb + (ABUF(s) + ldRow * HS + ldCol) * 2;
        const uint32_t db = sb + (BBUF(s) + ldRow * HS + ldCol) * 2;
        CP_ASYNC16(da,      ap);
        CP_ASYNC16(da + 16, ap + 8);
        CP_ASYNC16(db,      bp);
        CP_ASYNC16(db + 16, bp + 8);
    };

    const int lane16 = lane & 15;
    const int lhi    = (lane >> 4) * 8;    // +8 halfs for second k-chunk

    const int nT = K / 32;
    issue(0); CP_COMMIT();
    issue(1); CP_COMMIT();
    issue(2); CP_COMMIT();

    for (int t = 0; t < nT; t++) {
        CP_WAIT2();
        __syncthreads();
        const int s = t & 3;
        const uint32_t aBase = sb + ABUF(s) * 2;
        const uint32_t bBase = sb + BBUF(s) * 2;

        #pragma unroll
        for (int kk = 0; kk < 2; kk++) {      // two k16 steps
            unsigned af0[4], af1[4];
            LDSM_X4(af0[0], af0[1], af0[2], af0[3],
                    aBase + ((wm + lane16) * HS + lhi + 16 * kk) * 2);
            LDSM_X4(af1[0], af1[1], af1[2], af1[3],
                    aBase + ((wm + 16 + lane16) * HS + lhi + 16 * kk) * 2);
            #pragma unroll
            for (int p = 0; p < 4; p++) {     // 16-n groups
                unsigned bf[4];
                LDSM_X4(bf[0], bf[1], bf[2], bf[3],
                        bBase + ((wn + 16 * p + lane16) * HS + lhi + 16 * kk) * 2);
                mma_f16(acc[0][2 * p],     af0, bf[0], bf[2]);
                mma_f16(acc[1][2 * p],     af1, bf[0], bf[2]);
                mma_f16(acc[0][2 * p + 1], af0, bf[1], bf[3]);
                mma_f16(acc[1][2 * p + 1], af1, bf[1], bf[3]);
            }
        }
        if (t + 3 < nT) issue(t + 3);
        CP_COMMIT();
    }

    #pragma unroll
    for (int j = 0; j < 8; j++) {
        const int col = bn + wn + 8 * j + 2 * lc;
        const float bs0 = bias[col], bs1 = bias[col + 1];
        #pragma unroll
        for (int i = 0; i < 2; i++) {
            const int row = bm + wm + 16 * i + lr;
            if (HALF_OUT) {
                __half* Ch = (__half*)Cv;
                *(__half2*)(Ch + (size_t)row * N + col) =
                    __floats2half2_rn(acc[i][j][0] + bs0, acc[i][j][1] + bs1);
                *(__half2*)(Ch + (size_t)(row + 8) * N + col) =
                    __floats2half2_rn(acc[i][j][2] + bs0, acc[i][j][3] + bs1);
            } else {
                float* Cf = (float*)Cv;
                *(float2*)(Cf + (size_t)row * N + col) =
                    make_float2(acc[i][j][0] + bs0, acc[i][j][1] + bs1);
                *(float2*)(Cf + (size_t)(row + 8) * N + col) =
                    make_float2(acc[i][j][2] + bs0, acc[i][j][3] + bs1);
            }
        }
    }
}

// ---------------------------------------------------------------------------
// FP16 flash attention: 256 threads (8 warps) = 128 q-rows, 64-key tiles.
// 2-stage cp.async, 2 CTAs/SM. mma m16n8k16.
// P stays in REGISTERS: the S C-fragment lane layout equals the PV A-fragment
// layout (a0=pack(c0,c1)[j=2kk], a1=pack(c2,c3)[j=2kk], a2/a3 same of j=2kk+1),
// so PV A-frags are __floats2half2_rn packs of sAcc — no smem bounce, no
// syncwarp, 18KB less smem. Values bit-identical to the old store->ldmatrix.
// ---------------------------------------------------------------------------
#define AHS 72
#define KSTG (64 * AHS)                            // 4608 halfs
#define KOFF(s) ((s) * 2 * KSTG)
#define VOFF(s) ((s) * 2 * KSTG + KSTG)
#define AT_SMEM (2 * 2 * KSTG * 2)                 // 36864 B

__global__ void __launch_bounds__(256, 2)
k_attn()
{
    extern __shared__ __half smh[];
    const uint32_t sb = smem_u32(smh);
    const int tid  = threadIdx.x;
    const int wid  = tid >> 5;
    const int lane = tid & 31;
    const int lr   = lane >> 2;
    const int lc   = lane & 3;
    const int bh   = blockIdx.x;
    const int b    = bh >> 4;
    const int h    = bh & 15;
    const int q0   = blockIdx.y * 128;

    const __half* base = g_qkv + (size_t)b * S_LEN * QKV_N;
    const __half* vtb  = g_vt + (size_t)bh * DK * S_LEN;
    const int ho = h * (3 * DK);

    // Q fragments from gmem, x0.125 (exact pow2 in fp16)
    unsigned Qf[4][4];
    {
        const __half2 scl = __float2half2_rn(0.125f);
        const __half* qr0 = base + (size_t)(q0 + wid * 16 + lr) * QKV_N + ho;
        const __half* qr1 = qr0 + (size_t)8 * QKV_N;
        #pragma unroll
        for (int kk = 0; kk < 4; kk++) {
            Qf[kk][0] = h2u(__hmul2(*(const __half2*)(qr0 + 16 * kk + 2 * lc), scl));
            Qf[kk][1] = h2u(__hmul2(*(const __half2*)(qr1 + 16 * kk + 2 * lc), scl));
            Qf[kk][2] = h2u(__hmul2(*(const __half2*)(qr0 + 16 * kk + 2 * lc + 8), scl));
            Qf[kk][3] = h2u(__hmul2(*(const __half2*)(qr1 + 16 * kk + 2 * lc + 8), scl));
        }
    }

    // cp.async: K and V^T each 64 rows x 8 chunks (512); 2 chunks/thread each
    auto issue = [&](int t) {
        const int s  = t & 1;
        const int r  = tid >> 2;            // row 0..63
        const int cb = (tid & 3) * 16;      // half col 0/16/32/48
        {   // K tile: rows = keys, cols = dims
            const __half* kp = base + (size_t)(t * 64 + r) * QKV_N + ho + DK + cb;
            const uint32_t dk_ = sb + (KOFF(s) + r * AHS + cb) * 2;
            CP_ASYNC16(dk_,      kp);
            CP_ASYNC16(dk_ + 16, kp + 8);
        }
        {   // V^T tile: rows = dims, cols = keys
            const __half* vp = vtb + (size_t)r * S_LEN + t * 64 + cb;
            const uint32_t dv = sb + (VOFF(s) + r * AHS + cb) * 2;
            CP_ASYNC16(dv,      vp);
            CP_ASYNC16(dv + 16, vp + 8);
        }
    };

    float oAcc[8][4];
    #pragma unroll
    for (int j = 0; j < 8; j++)
        #pragma unroll
        for (int q = 0; q < 4; q++) oAcc[j][q] = 0.f;
    float m0 = -1e30f, m1 = -1e30f, l0 = 0.f, l1 = 0.f;

    const int lane16 = lane & 15;
    const int lhi    = (lane >> 4) * 8;

    const int nT = S_LEN / 64;
    issue(0); CP_COMMIT();

    for (int t = 0; t < nT; t++) {
        CP_WAIT0();
        __syncthreads();
        // buffer (t+1)&1 was released by the sync above (compute t-1 done)
        if (t + 1 < nT) issue(t + 1);
        CP_COMMIT();

        const int s = t & 1;
        const uint32_t kBase = sb + KOFF(s) * 2;
        const uint32_t vBase = sb + VOFF(s) * 2;

        // S = Q @ K^T  (16 q x 64 keys per warp)
        float sAcc[8][4];
        #pragma unroll
        for (int j = 0; j < 8; j++)
            sAcc[j][0] = sAcc[j][1] = sAcc[j][2] = sAcc[j][3] = 0.f;
        #pragma unroll
        for (int kk = 0; kk < 4; kk++) {
            #pragma unroll
            for (int p = 0; p < 4; p++) {
                unsigned bf[4];
                LDSM_X4(bf[0], bf[1], bf[2], bf[3],
                        kBase + ((16 * p + lane16) * AHS + lhi + 16 * kk) * 2);
                mma_f16(sAcc[2 * p],     Qf[kk], bf[0], bf[2]);
                mma_f16(sAcc[2 * p + 1], Qf[kk], bf[1], bf[3]);
            }
        }

        // online softmax (rows lr and lr+8)
        float mx0 = -1e30f, mx1 = -1e30f;
        #pragma unroll
        for (int j = 0; j < 8; j++) {
            mx0 = fmaxf(mx0, fmaxf(sAcc[j][0], sAcc[j][1]));
            mx1 = fmaxf(mx1, fmaxf(sAcc[j][2], sAcc[j][3]));
        }
        mx0 = fmaxf(mx0, __shfl_xor_sync(0xffffffffu, mx0, 1));
        mx0 = fmaxf(mx0, __shfl_xor_sync(0xffffffffu, mx0, 2));
        mx1 = fmaxf(mx1, __shfl_xor_sync(0xffffffffu, mx1, 1));
        mx1 = fmaxf(mx1, __shfl_xor_sync(0xffffffffu, mx1, 2));

        const float mn0 = fmaxf(m0, mx0), mn1 = fmaxf(m1, mx1);
        const float cor0 = __expf(m0 - mn0), cor1 = __expf(m1 - mn1);
        m0 = mn0; m1 = mn1;

        float s0 = 0.f, s1 = 0.f;
        #pragma unroll
        for (int j = 0; j < 8; j++) {
            sAcc[j][0] = __expf(sAcc[j][0] - mn0); s0 += sAcc[j][0];
            sAcc[j][1] = __expf(sAcc[j][1] - mn0); s0 += sAcc[j][1];
            sAcc[j][2] = __expf(sAcc[j][2] - mn1); s1 += sAcc[j][2];
            sAcc[j][3] = __expf(sAcc[j][3] - mn1); s1 += sAcc[j][3];
        }
        s0 += __shfl_xor_sync(0xffffffffu, s0, 1);
        s0 += __shfl_xor_sync(0xffffffffu, s0, 2);
        s1 += __shfl_xor_sync(0xffffffffu, s1, 1);
        s1 += __shfl_xor_sync(0xffffffffu, s1, 2);
        l0 = l0 * cor0 + s0;
        l1 = l1 * cor1 + s1;

        #pragma unroll
        for (int j = 0; j < 8; j++) {
            oAcc[j][0] *= cor0; oAcc[j][1] *= cor0;
            oAcc[j][2] *= cor1; oAcc[j][3] *= cor1;
        }

        // O += P @ V: P A-fragments built directly from sAcc registers
        #pragma unroll
        for (int kk = 0; kk < 4; kk++) {      // 16-key steps
            unsigned pf[4];
            pf[0] = h2u(__floats2half2_rn(sAcc[2 * kk][0],     sAcc[2 * kk][1]));
            pf[1] = h2u(__floats2half2_rn(sAcc[2 * kk][2],     sAcc[2 * kk][3]));
            pf[2] = h2u(__floats2half2_rn(sAcc[2 * kk + 1][0], sAcc[2 * kk + 1][1]));
            pf[3] = h2u(__floats2half2_rn(sAcc[2 * kk + 1][2], sAcc[2 * kk + 1][3]));
            #pragma unroll
            for (int p = 0; p < 4; p++) {     // 16-d groups
                unsigned bf[4];
                LDSM_X4(bf[0], bf[1], bf[2], bf[3],
                        vBase + ((16 * p + lane16) * AHS + lhi + 16 * kk) * 2);
                mma_f16(oAcc[2 * p],     pf, bf[0], bf[2]);
                mma_f16(oAcc[2 * p + 1], pf, bf[1], bf[3]);
            }
        }
    }

    // epilogue: normalize, convert half, store head-interleaved ctx
    const float inv0 = 1.f / l0, inv1 = 1.f / l1;
    __half* orow0 = g_ctx + (size_t)(b * S_LEN + q0 + wid * 16 + lr) * D_MODEL + h * DK;
    __half* orow1 = orow0 + (size_t)8 * D_MODEL;
    #pragma unroll
    for (int j = 0; j < 8; j++) {
        const int colo = 8 * j + 2 * lc;
        *(__half2*)(orow0 + colo) =
            __floats2half2_rn(oAcc[j][0] * inv0, oAcc[j][1] * inv0);
        *(__half2*)(orow1 + colo) =
            __floats2half2_rn(oAcc[j][2] * inv1, oAcc[j][3] * inv1);
    }
}

// ---------------------------------------------------------------------------
extern "C" void kernel_launch(void* const* d_in, const int* in_sizes, int n_in,
                              void* d_out, int out_size)
{
    (void)in_sizes; (void)n_in; (void)out_size;
    const float* x     = (const float*)d_in[0];
    const float* W_qkv = (const float*)d_in[1];
    const float* b_qkv = (const float*)d_in[2];
    const float* W_o   = (const float*)d_in[3];
    const float* b_o   = (const float*)d_in[4];
    float* out = (float*)d_out;

    static __half *p_qkv = nullptr, *p_ctx, *p_xh, *p_wqt, *p_wot;
    if (!p_qkv) {
        cudaGetSymbolAddress((void**)&p_qkv, g_qkv);
        cudaGetSymbolAddress((void**)&p_ctx, g_ctx);
        cudaGetSymbolAddress((void**)&p_xh,  g_xh);
        cudaGetSymbolAddress((void**)&p_wqt, g_wqt);
        cudaGetSymbolAddress((void**)&p_wot, g_wot);
        cudaFuncSetAttribute(k_gemm<true>,
                             cudaFuncAttributeMaxDynamicSharedMemorySize, GT_SMEM);
        cudaFuncSetAttribute(k_gemm<false>,
                             cudaFuncAttributeMaxDynamicSharedMemorySize, GT_SMEM);
        cudaFuncSetAttribute(k_attn,
                             cudaFuncAttributeMaxDynamicSharedMemorySize, AT_SMEM);
    }

    // prep: x -> half; weights -> transposed half
    k_h4<<<(M_ROWS * D_MODEL / 4 + 255) / 256, 256>>>(x, p_xh, M_ROWS * D_MODEL / 4);
    k_trT<<<dim3(QKV_N / 32, D_MODEL / 32), dim3(32, 8)>>>(W_qkv, p_wqt, D_MODEL, QKV_N);
    k_trT<<<dim3(D_MODEL / 32, D_MODEL / 32), dim3(32, 8)>>>(W_o, p_wot, D_MODEL, D_MODEL);

    k_gemm<true><<<dim3(QKV_N / 128, M_ROWS / 128), 256, GT_SMEM>>>(
        p_xh, p_wqt, b_qkv, p_qkv, QKV_N, D_MODEL);
    k_vtrans<<<dim3(S_LEN / 32, DK / 32, B_SZ * NHEADS), dim3(32, 8)>>>();
    k_attn<<<dim3(B_SZ * NHEADS, S_LEN / 128), 256, AT_SMEM>>>();
    k_gemm<false><<<dim3(D_MODEL / 128, M_ROWS / 128), 256, GT_SMEM>>>(
        p_ctx, p_wot, b_o, out, D_MODEL, D_MODEL);
}